// round 8
// baseline (speedup 1.0000x reference)
#include <cuda_runtime.h>
#include <cstdint>

// ALNNLayer fused. thread = (k-group of 4|3) x (8 b) x (1 d); block = 256 thr (4 kg x 64 d).
// L-reduction via coalesced fp32 atomicAdd into a 213KB L2-resident accumulator.
// Shapes: X,T,M,DT: [B=64, L=200, D=64]; alpha: [K=13]; w_v,b_t: [K,L,D];
//         w_t: [K,L,D,4]; b_v: [K,1,D]; out: [B,K,D].
// Math per (b,k,l,d):
//   kern  = exp(-relu(alpha_k)*|T-4k|) = 2^(-|a*T + na|), a = relu(alpha)*log2e, na = -a*4k
//   inten = kern * relu(X)
//   lat   = relu(wt0*X + wt1*DT + wt2*inten + wt3*M + 4*b_t)
//   out[b,k,d] = relu( sum_l w_v*lat + 200*b_v[k,d] )

#define KREF 13
#define LN   200
#define DN   64
#define BN   64
#define BT   8
#define LC   4
#define NCH  (LN / LC)          // 50
#define NBT  (BN / BT)          // 8
#define BKD  (BN * KREF * DN)   // 53248
#define KT   4                  // max k's per k-group

// accumulator[b][k][d] — starts zero (static init); biaszero re-zeroes after reading.
__device__ __align__(16) float g_accum[BKD];

__device__ __forceinline__ float ex2f(float x) {
    float r; asm("ex2.approx.ftz.f32 %0, %1;" : "=f"(r) : "f"(x)); return r;
}

__global__ __launch_bounds__(256, 2)
void alnn_main(const float* __restrict__ X, const float* __restrict__ T,
               const float* __restrict__ M, const float* __restrict__ DT,
               const float* __restrict__ alpha,
               const float* __restrict__ w_v, const float* __restrict__ w_t,
               const float* __restrict__ b_t, int cbase)
{
    const int chunk = cbase + blockIdx.x;    // l-chunk
    const int btile = blockIdx.y;            // 0..7
    const int tid   = threadIdx.x;
    const int kgi   = tid >> 6;              // 0..3
    const int d     = tid & 63;              // 0..63
    const int kbase = kgi ? (3 * kgi + 1) : 0;   // 0,4,7,10
    const int kcnt  = kgi ? 3 : 4;               // 4,3,3,3
    const int b0    = btile * BT;
    const int l0    = chunk * LC;

    // per-k exp constants
    float a[KT], na[KT];
    #pragma unroll
    for (int kk = 0; kk < KT; kk++) {
        if (kk < kcnt) {
            const int k = kbase + kk;
            const float av = fmaxf(__ldg(alpha + k), 0.0f) * 1.4426950408889634f;
            a[kk]  = av;
            na[kk] = -av * (4.0f * (float)k);
        } else { a[kk] = 0.0f; na[kk] = 0.0f; }
    }

    float acc[KT][BT];
    #pragma unroll
    for (int kk = 0; kk < KT; kk++)
        #pragma unroll
        for (int bi = 0; bi < BT; bi++) acc[kk][bi] = 0.0f;

    const size_t bstr = (size_t)LN * DN;

    #pragma unroll
    for (int li = 0; li < LC; li++) {
        const int l = l0 + li;
        const size_t ibase = (size_t)l * DN + d + (size_t)b0 * bstr;

        float x[BT], t[BT], m[BT], dt[BT], rx[BT];
        #pragma unroll
        for (int bi = 0; bi < BT; bi++) {
            const size_t o = ibase + (size_t)bi * bstr;
            x[bi]  = __ldg(X  + o);
            t[bi]  = __ldg(T  + o);
            m[bi]  = __ldg(M  + o);
            dt[bi] = __ldg(DT + o);
        }
        #pragma unroll
        for (int bi = 0; bi < BT; bi++) rx[bi] = fmaxf(x[bi], 0.0f);

        #pragma unroll
        for (int kk = 0; kk < KT; kk++) {
            if (kk < kcnt) {
                const size_t woff = ((size_t)(kbase + kk) * LN + l) * DN + d;
                const float  wv  = __ldg(w_v + woff);
                const float  bt4 = 4.0f * __ldg(b_t + woff);
                const float4 wt  = __ldg(reinterpret_cast<const float4*>(w_t) + woff);
                const float  ak = a[kk], nak = na[kk];

                #pragma unroll
                for (int bi = 0; bi < BT; bi++) {
                    const float w  = fmaf(t[bi], ak, nak);
                    const float e  = ex2f(-fabsf(w));        // 2^(-|w|)
                    const float in = e * rx[bi];
                    const float s  = fmaf(wt.x, x[bi],
                                     fmaf(wt.y, dt[bi],
                                     fmaf(wt.z, in,
                                     fmaf(wt.w, m[bi], bt4))));
                    acc[kk][bi] = fmaf(wv, fmaxf(s, 0.0f), acc[kk][bi]);
                }
            }
        }
    }

    // coalesced fp32 reductions into the L2-resident accumulator
    #pragma unroll
    for (int kk = 0; kk < KT; kk++) {
        if (kk < kcnt) {
            #pragma unroll
            for (int bi = 0; bi < BT; bi++) {
                atomicAdd(&g_accum[((size_t)(b0 + bi) * KREF + (kbase + kk)) * DN + d],
                          acc[kk][bi]);
            }
        }
    }
}

// bias + relu epilogue; also re-zeroes the accumulator for the next replay.
__global__ __launch_bounds__(256)
void alnn_biaszero(const float* __restrict__ b_v, float* __restrict__ out)
{
    const int g = blockIdx.x * 256 + threadIdx.x;   // over BKD/4 = 13312
    if (g >= BKD / 4) return;
    const int dq = (g & 15) * 4;
    const int bk = g >> 4;
    const int k  = bk % KREF;

    float4* ap = reinterpret_cast<float4*>(g_accum + (size_t)bk * DN + dq);
    const float4 s  = *ap;
    const float4 bv = *reinterpret_cast<const float4*>(b_v + k * DN + dq);
    float4 o;
    o.x = fmaxf(fmaf(200.f, bv.x, s.x), 0.f);
    o.y = fmaxf(fmaf(200.f, bv.y, s.y), 0.f);
    o.z = fmaxf(fmaf(200.f, bv.z, s.z), 0.f);
    o.w = fmaxf(fmaf(200.f, bv.w, s.w), 0.f);
    *reinterpret_cast<float4*>(out + (size_t)bk * DN + dq) = o;
    *ap = make_float4(0.f, 0.f, 0.f, 0.f);          // ready for next call
}

extern "C" void kernel_launch(void* const* d_in, const int* in_sizes, int n_in,
                              void* d_out, int out_size)
{
    // metadata order: X, T, M, DT, alpha, w_v, w_t, b_v, b_t
    const float* X     = (const float*)d_in[0];
    const float* T     = (const float*)d_in[1];
    const float* M     = (const float*)d_in[2];
    const float* DT    = (const float*)d_in[3];
    const float* alpha = (const float*)d_in[4];
    const float* w_v   = (const float*)d_in[5];
    const float* w_t   = (const float*)d_in[6];
    const float* b_v   = (const float*)d_in[7];
    const float* b_t   = (const float*)d_in[8];
    float* out = (float*)d_out;

    dim3 grid(NCH / 2, NBT);
    alnn_main<<<grid, 256>>>(X, T, M, DT, alpha, w_v, w_t, b_t, 0);
    alnn_main<<<grid, 256>>>(X, T, M, DT, alpha, w_v, w_t, b_t, NCH / 2);
    alnn_biaszero<<<(BKD / 4 + 255) / 256, 256>>>(b_v, out);
}

// round 9
// speedup vs baseline: 1.1194x; 1.1194x over previous
#include <cuda_runtime.h>
#include <cstdint>

// ALNNLayer fused. thread = (k-group of 4|3) x (8 b) x (1 d); block = 256 thr (4 kg x 64 d).
// Single launch, grid(100,8)=800 blocks for full residency. L-reduction via coalesced
// fp32 atomicAdd into a 213KB L2-resident accumulator.
// Shapes: X,T,M,DT: [B=64, L=200, D=64]; alpha: [K=13]; w_v,b_t: [K,L,D];
//         w_t: [K,L,D,4]; b_v: [K,1,D]; out: [B,K,D].
// Math per (b,k,l,d):
//   kern  = exp(-relu(alpha_k)*|T-4k|) = 2^(-|a*T + na|), a = relu(alpha)*log2e, na = -a*4k
//   inten = kern * relu(X)
//   lat   = relu(wt0*X + wt1*DT + wt2*inten + wt3*M + 4*b_t)
//   out[b,k,d] = relu( sum_l w_v*lat + 200*b_v[k,d] )

#define KREF 13
#define LN   200
#define DN   64
#define BN   64
#define BT   8
#define LC   2
#define NCH  (LN / LC)          // 100
#define NBT  (BN / BT)          // 8
#define BKD  (BN * KREF * DN)   // 53248
#define KT   4                  // max k's per k-group

// accumulator[b][k][d] — starts zero (static init); biaszero re-zeroes after reading.
__device__ __align__(16) float g_accum[BKD];

__device__ __forceinline__ float ex2f(float x) {
    float r; asm("ex2.approx.ftz.f32 %0, %1;" : "=f"(r) : "f"(x)); return r;
}

__global__ __launch_bounds__(256, 2)
void alnn_main(const float* __restrict__ X, const float* __restrict__ T,
               const float* __restrict__ M, const float* __restrict__ DT,
               const float* __restrict__ alpha,
               const float* __restrict__ w_v, const float* __restrict__ w_t,
               const float* __restrict__ b_t)
{
    const int chunk = blockIdx.x;            // 0..99
    const int btile = blockIdx.y;            // 0..7
    const int tid   = threadIdx.x;
    const int kgi   = tid >> 6;              // 0..3
    const int d     = tid & 63;              // 0..63
    const int kbase = kgi ? (3 * kgi + 1) : 0;   // 0,4,7,10
    const int kcnt  = kgi ? 3 : 4;               // 4,3,3,3
    const int b0    = btile * BT;
    const int l0    = chunk * LC;

    // per-k exp constants
    float a[KT], na[KT];
    #pragma unroll
    for (int kk = 0; kk < KT; kk++) {
        if (kk < kcnt) {
            const int k = kbase + kk;
            const float av = fmaxf(__ldg(alpha + k), 0.0f) * 1.4426950408889634f;
            a[kk]  = av;
            na[kk] = -av * (4.0f * (float)k);
        } else { a[kk] = 0.0f; na[kk] = 0.0f; }
    }

    float acc[KT][BT];
    #pragma unroll
    for (int kk = 0; kk < KT; kk++)
        #pragma unroll
        for (int bi = 0; bi < BT; bi++) acc[kk][bi] = 0.0f;

    const size_t bstr = (size_t)LN * DN;

    #pragma unroll
    for (int li = 0; li < LC; li++) {
        const int l = l0 + li;
        const size_t ibase = (size_t)l * DN + d + (size_t)b0 * bstr;

        float x[BT], t[BT], m[BT], dt[BT], rx[BT];
        #pragma unroll
        for (int bi = 0; bi < BT; bi++) {
            const size_t o = ibase + (size_t)bi * bstr;
            x[bi]  = __ldg(X  + o);
            t[bi]  = __ldg(T  + o);
            m[bi]  = __ldg(M  + o);
            dt[bi] = __ldg(DT + o);
        }
        #pragma unroll
        for (int bi = 0; bi < BT; bi++) rx[bi] = fmaxf(x[bi], 0.0f);

        #pragma unroll
        for (int kk = 0; kk < KT; kk++) {
            if (kk < kcnt) {
                const size_t woff = ((size_t)(kbase + kk) * LN + l) * DN + d;
                const float  wv  = __ldg(w_v + woff);
                const float  bt4 = 4.0f * __ldg(b_t + woff);
                const float4 wt  = __ldg(reinterpret_cast<const float4*>(w_t) + woff);
                const float  ak = a[kk], nak = na[kk];

                #pragma unroll
                for (int bi = 0; bi < BT; bi++) {
                    const float w  = fmaf(t[bi], ak, nak);
                    const float e  = ex2f(-fabsf(w));        // 2^(-|w|)
                    const float in = e * rx[bi];
                    const float s  = fmaf(wt.x, x[bi],
                                     fmaf(wt.y, dt[bi],
                                     fmaf(wt.z, in,
                                     fmaf(wt.w, m[bi], bt4))));
                    acc[kk][bi] = fmaf(wv, fmaxf(s, 0.0f), acc[kk][bi]);
                }
            }
        }
    }

    // coalesced fp32 reductions into the L2-resident accumulator
    #pragma unroll
    for (int kk = 0; kk < KT; kk++) {
        if (kk < kcnt) {
            #pragma unroll
            for (int bi = 0; bi < BT; bi++) {
                atomicAdd(&g_accum[((size_t)(b0 + bi) * KREF + (kbase + kk)) * DN + d],
                          acc[kk][bi]);
            }
        }
    }
}

// bias + relu epilogue; also re-zeroes the accumulator for the next replay.
__global__ __launch_bounds__(256)
void alnn_biaszero(const float* __restrict__ b_v, float* __restrict__ out)
{
    const int g = blockIdx.x * 256 + threadIdx.x;   // over BKD/4 = 13312
    if (g >= BKD / 4) return;
    const int dq = (g & 15) * 4;
    const int bk = g >> 4;
    const int k  = bk % KREF;

    float4* ap = reinterpret_cast<float4*>(g_accum + (size_t)bk * DN + dq);
    const float4 s  = *ap;
    const float4 bv = *reinterpret_cast<const float4*>(b_v + k * DN + dq);
    float4 o;
    o.x = fmaxf(fmaf(200.f, bv.x, s.x), 0.f);
    o.y = fmaxf(fmaf(200.f, bv.y, s.y), 0.f);
    o.z = fmaxf(fmaf(200.f, bv.z, s.z), 0.f);
    o.w = fmaxf(fmaf(200.f, bv.w, s.w), 0.f);
    *reinterpret_cast<float4*>(out + (size_t)bk * DN + dq) = o;
    *ap = make_float4(0.f, 0.f, 0.f, 0.f);          // ready for next call
}

extern "C" void kernel_launch(void* const* d_in, const int* in_sizes, int n_in,
                              void* d_out, int out_size)
{
    // metadata order: X, T, M, DT, alpha, w_v, w_t, b_v, b_t
    const float* X     = (const float*)d_in[0];
    const float* T     = (const float*)d_in[1];
    const float* M     = (const float*)d_in[2];
    const float* DT    = (const float*)d_in[3];
    const float* alpha = (const float*)d_in[4];
    const float* w_v   = (const float*)d_in[5];
    const float* w_t   = (const float*)d_in[6];
    const float* b_v   = (const float*)d_in[7];
    const float* b_t   = (const float*)d_in[8];
    float* out = (float*)d_out;

    dim3 grid(NCH, NBT);
    alnn_main<<<grid, 256>>>(X, T, M, DT, alpha, w_v, w_t, b_t);
    alnn_biaszero<<<(BKD / 4 + 255) / 256, 256>>>(b_v, out);
}

// round 10
// speedup vs baseline: 1.1364x; 1.0152x over previous
#include <cuda_runtime.h>
#include <cstdint>

// ALNNLayer fused. thread = (k-group of 4|3) x (4 b) x (1 d); block = 256 thr (4 kg x 64 d).
// 1600-block grid, 3 blocks/SM (24 warps/SM). L-reduction via coalesced fp32 atomicAdd
// into a 213KB L2-resident accumulator.
// Shapes: X,T,M,DT: [B=64, L=200, D=64]; alpha: [K=13]; w_v,b_t: [K,L,D];
//         w_t: [K,L,D,4]; b_v: [K,1,D]; out: [B,K,D].
// Math per (b,k,l,d):
//   kern  = exp(-relu(alpha_k)*|T-4k|) = 2^(-|a*T + na|), a = relu(alpha)*log2e, na = -a*4k
//   inten = kern * relu(X)
//   lat   = relu(wt0*X + wt1*DT + wt2*inten + wt3*M + 4*b_t)
//   out[b,k,d] = relu( sum_l w_v*lat + 200*b_v[k,d] )

#define KREF 13
#define LN   200
#define DN   64
#define BN   64
#define BT   4
#define LC   2
#define NCH  (LN / LC)          // 100
#define NBT  (BN / BT)          // 16
#define BKD  (BN * KREF * DN)   // 53248
#define KT   4                  // max k's per k-group

// accumulator[b][k][d] — starts zero (static init); biaszero re-zeroes after reading.
__device__ __align__(16) float g_accum[BKD];

__device__ __forceinline__ float ex2f(float x) {
    float r; asm("ex2.approx.ftz.f32 %0, %1;" : "=f"(r) : "f"(x)); return r;
}

__global__ __launch_bounds__(256, 3)
void alnn_main(const float* __restrict__ X, const float* __restrict__ T,
               const float* __restrict__ M, const float* __restrict__ DT,
               const float* __restrict__ alpha,
               const float* __restrict__ w_v, const float* __restrict__ w_t,
               const float* __restrict__ b_t)
{
    const int chunk = blockIdx.x;            // 0..99
    const int btile = blockIdx.y;            // 0..15
    const int tid   = threadIdx.x;
    const int kgi   = tid >> 6;              // 0..3
    const int d     = tid & 63;              // 0..63
    const int kbase = kgi ? (3 * kgi + 1) : 0;   // 0,4,7,10
    const int kcnt  = kgi ? 3 : 4;               // 4,3,3,3
    const int b0    = btile * BT;
    const int l0    = chunk * LC;

    // per-k exp constants
    float a[KT], na[KT];
    #pragma unroll
    for (int kk = 0; kk < KT; kk++) {
        if (kk < kcnt) {
            const int k = kbase + kk;
            const float av = fmaxf(__ldg(alpha + k), 0.0f) * 1.4426950408889634f;
            a[kk]  = av;
            na[kk] = -av * (4.0f * (float)k);
        } else { a[kk] = 0.0f; na[kk] = 0.0f; }
    }

    float acc[KT][BT];
    #pragma unroll
    for (int kk = 0; kk < KT; kk++)
        #pragma unroll
        for (int bi = 0; bi < BT; bi++) acc[kk][bi] = 0.0f;

    const size_t bstr = (size_t)LN * DN;

    #pragma unroll
    for (int li = 0; li < LC; li++) {
        const int l = l0 + li;
        const size_t ibase = (size_t)l * DN + d + (size_t)b0 * bstr;

        float x[BT], t[BT], m[BT], dt[BT], rx[BT];
        #pragma unroll
        for (int bi = 0; bi < BT; bi++) {
            const size_t o = ibase + (size_t)bi * bstr;
            x[bi]  = __ldg(X  + o);
            t[bi]  = __ldg(T  + o);
            m[bi]  = __ldg(M  + o);
            dt[bi] = __ldg(DT + o);
        }
        #pragma unroll
        for (int bi = 0; bi < BT; bi++) rx[bi] = fmaxf(x[bi], 0.0f);

        #pragma unroll
        for (int kk = 0; kk < KT; kk++) {
            if (kk < kcnt) {
                const size_t woff = ((size_t)(kbase + kk) * LN + l) * DN + d;
                const float  wv  = __ldg(w_v + woff);
                const float  bt4 = 4.0f * __ldg(b_t + woff);
                const float4 wt  = __ldg(reinterpret_cast<const float4*>(w_t) + woff);
                const float  ak = a[kk], nak = na[kk];

                #pragma unroll
                for (int bi = 0; bi < BT; bi++) {
                    const float w  = fmaf(t[bi], ak, nak);
                    const float e  = ex2f(-fabsf(w));        // 2^(-|w|)
                    const float in = e * rx[bi];
                    const float s  = fmaf(wt.x, x[bi],
                                     fmaf(wt.y, dt[bi],
                                     fmaf(wt.z, in,
                                     fmaf(wt.w, m[bi], bt4))));
                    acc[kk][bi] = fmaf(wv, fmaxf(s, 0.0f), acc[kk][bi]);
                }
            }
        }
    }

    // coalesced fp32 reductions into the L2-resident accumulator
    #pragma unroll
    for (int kk = 0; kk < KT; kk++) {
        if (kk < kcnt) {
            #pragma unroll
            for (int bi = 0; bi < BT; bi++) {
                atomicAdd(&g_accum[((size_t)(b0 + bi) * KREF + (kbase + kk)) * DN + d],
                          acc[kk][bi]);
            }
        }
    }
}

// bias + relu epilogue; one scalar per thread (208 blocks). Re-zeroes accumulator.
__global__ __launch_bounds__(256)
void alnn_biaszero(const float* __restrict__ b_v, float* __restrict__ out)
{
    const int g = blockIdx.x * 256 + threadIdx.x;   // over BKD = 53248
    if (g >= BKD) return;
    const int d  = g & 63;
    const int k  = (g >> 6) % KREF;

    const float s  = g_accum[g];
    const float bv = __ldg(b_v + k * DN + d);
    out[g] = fmaxf(fmaf(200.f, bv, s), 0.f);
    g_accum[g] = 0.f;                               // ready for next call
}

extern "C" void kernel_launch(void* const* d_in, const int* in_sizes, int n_in,
                              void* d_out, int out_size)
{
    // metadata order: X, T, M, DT, alpha, w_v, w_t, b_v, b_t
    const float* X     = (const float*)d_in[0];
    const float* T     = (const float*)d_in[1];
    const float* M     = (const float*)d_in[2];
    const float* DT    = (const float*)d_in[3];
    const float* alpha = (const float*)d_in[4];
    const float* w_v   = (const float*)d_in[5];
    const float* w_t   = (const float*)d_in[6];
    const float* b_v   = (const float*)d_in[7];
    const float* b_t   = (const float*)d_in[8];
    float* out = (float*)d_out;

    dim3 grid(NCH, NBT);
    alnn_main<<<grid, 256>>>(X, T, M, DT, alpha, w_v, w_t, b_t);
    alnn_biaszero<<<(BKD + 255) / 256, 256>>>(b_v, out);
}